// round 16
// baseline (speedup 1.0000x reference)
#include <cuda_runtime.h>
#include <cuda_bf16.h>
#include <cstdint>

// ---------------------------------------------------------------------------
// LocallyGroupedAttn. R16: GEMMs -> 4-stage BK=16 cp.async pipeline (1 sync /
// iteration, 2 tiles in flight). Attn + prep identical to R15 (598.1us best).
// ---------------------------------------------------------------------------

#define B_    8
#define H_    112
#define W_    112
#define C_    256
#define WS_   7
#define NH_   8
#define HD_   32
#define WS2_  49
#define BW_   (B_ * 16 * 16)     // 2048
#define M_    (BW_ * WS2_)       // 100352

__device__ uint32_t g_q[M_ * C_];     // packed bf16 hi|lo per element
__device__ uint32_t g_k[M_ * C_];
__device__ uint32_t g_v[M_ * C_];
__device__ float    g_o[M_ * C_];     // rounded+gathered x, then attn output
__device__ float    g_wq[768 * C_];   // rounded + k-permuted qkv weight
__device__ float    g_wp[C_ * C_];    // rounded proj weight

__device__ __forceinline__ int token_of(int m) {
    int bw  = m / WS2_;
    int t   = m - bw * WS2_;
    int b   = bw >> 8;
    int win = bw & 255;
    int ty  = t / WS_;
    int tx  = t - ty * WS_;
    int y   = (win >> 4) * WS_ + ty;
    int x   = (win & 15) * WS_ + tx;
    return (b * H_ + y) * W_ + x;
}

__device__ __forceinline__ float rtf(float f) {
    uint32_t u;
    asm("cvt.rna.tf32.f32 %0, %1;" : "=r"(u) : "f"(f));
    return __uint_as_float(u);
}

__device__ __forceinline__ uint32_t smem_u32(const void* p) {
    uint32_t a;
    asm("{ .reg .u64 t; cvta.to.shared.u64 t, %1; cvt.u32.u64 %0, t; }" : "=r"(a) : "l"(p));
    return a;
}

__device__ __forceinline__ void cp16(void* dst, const void* src) {
    asm volatile("cp.async.cg.shared.global [%0], [%1], 16;"
                 :: "r"(smem_u32(dst)), "l"(src));
}
#define CP_COMMIT() asm volatile("cp.async.commit_group;" ::: "memory")
#define CP_WAIT2()  asm volatile("cp.async.wait_group 2;" ::: "memory")

__device__ __forceinline__ void mma_tf32(float c[4], const uint32_t a[4], const uint32_t b[2]) {
    asm volatile(
        "mma.sync.aligned.m16n8k8.row.col.f32.tf32.tf32.f32 "
        "{%0,%1,%2,%3}, {%4,%5,%6,%7}, {%8,%9}, {%0,%1,%2,%3};"
        : "+f"(c[0]), "+f"(c[1]), "+f"(c[2]), "+f"(c[3])
        : "r"(a[0]), "r"(a[1]), "r"(a[2]), "r"(a[3]), "r"(b[0]), "r"(b[1]));
}

__device__ __forceinline__ void mma_bf16(float c[4], const uint32_t a[4], const uint32_t b[2]) {
    asm volatile(
        "mma.sync.aligned.m16n8k16.row.col.f32.bf16.bf16.f32 "
        "{%0,%1,%2,%3}, {%4,%5,%6,%7}, {%8,%9}, {%0,%1,%2,%3};"
        : "+f"(c[0]), "+f"(c[1]), "+f"(c[2]), "+f"(c[3])
        : "r"(a[0]), "r"(a[1]), "r"(a[2]), "r"(a[3]), "r"(b[0]), "r"(b[1]));
}

__device__ __forceinline__ uint32_t pkbf(float lo, float hi) {
    __nv_bfloat162 t = __floats2bfloat162_rn(lo, hi);
    return *(uint32_t*)&t;
}
__device__ __forceinline__ float bf2f(float x) {
    return __bfloat162float(__float2bfloat16_rn(x));
}
__device__ __forceinline__ uint32_t pack_hl(float f) {
    __nv_bfloat16 h = __float2bfloat16_rn(f);
    float hf = __bfloat162float(h);
    __nv_bfloat16 l = __float2bfloat16_rn(f - hf);
    return ((uint32_t)__bfloat16_as_ushort(h) << 16) | (uint32_t)__bfloat16_as_ushort(l);
}
#define HIPAIR(w0, w1) __byte_perm((w0), (w1), 0x7632)
#define LOPAIR(w0, w1) __byte_perm((w0), (w1), 0x5410)

// ---------------------------------------------------------------------------
// Fused prepass (R13)
// ---------------------------------------------------------------------------
#define PREP_X_CNT (M_ * 32)
#define PREP_WQ_CNT (768 * 32)
#define PREP_WP_CNT 16384
#define PREP_TOTAL (PREP_X_CNT + PREP_WQ_CNT + PREP_WP_CNT)

__global__ __launch_bounds__(256) void prep_all(const float* __restrict__ x,
                                                const float* __restrict__ qkv_w,
                                                const float* __restrict__ proj_w) {
    const int idx = blockIdx.x * 256 + threadIdx.x;
    if (idx < PREP_X_CNT) {
        const int m   = idx >> 5;
        const int grp = idx & 31;
        const float* src = x + (size_t)token_of(m) * C_ + grp * 8;
        const float4 a = *(const float4*)src;
        const float4 b = *(const float4*)(src + 4);
        float4 o0 = make_float4(rtf(a.x), rtf(b.x), rtf(a.y), rtf(b.y));
        float4 o1 = make_float4(rtf(a.z), rtf(b.z), rtf(a.w), rtf(b.w));
        float* dst = g_o + (size_t)m * C_ + grp * 8;
        *(float4*)dst       = o0;
        *(float4*)(dst + 4) = o1;
    } else if (idx < PREP_X_CNT + PREP_WQ_CNT) {
        const int j = idx - PREP_X_CNT;
        const int n = j >> 5, grp = j & 31;
        const float* src = qkv_w + (size_t)n * C_ + grp * 8;
        const float4 a = *(const float4*)src;
        const float4 b = *(const float4*)(src + 4);
        float4 o0 = make_float4(rtf(a.x), rtf(b.x), rtf(a.y), rtf(b.y));
        float4 o1 = make_float4(rtf(a.z), rtf(b.z), rtf(a.w), rtf(b.w));
        float* dst = g_wq + (size_t)n * C_ + grp * 8;
        *(float4*)dst       = o0;
        *(float4*)(dst + 4) = o1;
    } else {
        const int j = idx - PREP_X_CNT - PREP_WQ_CNT;
        const float4 v = ((const float4*)proj_w)[j];
        ((float4*)g_wp)[j] = make_float4(rtf(v.x), rtf(v.y), rtf(v.z), rtf(v.w));
    }
}

// ---------------------------------------------------------------------------
// GEMM (R16): block 128m x 128n, BK=16, 4-stage cp.async, ONE sync/iteration,
// warp tile 64x32 (8 warps = 2m x 4n), 2 CTAs/SM.
// PERM=1 (qkv): k-permuted operands, LDS.64 frags, stride 24 u32.
// PERM=0 (proj): plain operands, LDS.32 frags, stride 20.
// ---------------------------------------------------------------------------
template <int PERM>
__global__ __launch_bounds__(256, 2) void mma_gemm(const float* __restrict__ bias,
                                                   float* __restrict__ out) {
    constexpr int T       = PERM ? 24 : 20;
    constexpr int A_STAGE = 128 * T;                 // floats per A stage
    extern __shared__ char dsm[];
    float* As = (float*)dsm;                          // [4][128][T]
    float* Bs = As + 4 * A_STAGE;                     // [4][128][T]

    const int tid    = threadIdx.x;
    const int lane   = tid & 31;
    const int wid    = tid >> 5;
    const int warp_m = wid & 1;
    const int warp_n = wid >> 1;
    const int q      = lane & 3;
    const int g      = lane >> 2;
    const int n0     = blockIdx.x * 128;
    const int m0     = blockIdx.y * 128;

    const float* Aptr = g_o;
    const float* Bptr = PERM ? g_wq : g_wp;

    // issue stage st for k-offset k0 (A:128x16, B:128x16; 512 chunks each)
    auto issue = [&](int st, int k0) {
        float* Ad = As + st * A_STAGE;
        float* Bd = Bs + st * A_STAGE;
#pragma unroll
        for (int l = 0; l < 2; l++) {
            const int id  = tid + l * 256;            // 0..511
            const int row = id >> 2;
            const int c   = id & 3;
            cp16(Ad + row * T + c * 4, Aptr + (size_t)(m0 + row) * C_ + k0 + c * 4);
            cp16(Bd + row * T + c * 4, Bptr + (size_t)(n0 + row) * C_ + k0 + c * 4);
        }
    };

    float acc[4][4][4];
#pragma unroll
    for (int mt = 0; mt < 4; mt++)
#pragma unroll
        for (int nt = 0; nt < 4; nt++)
#pragma unroll
            for (int i = 0; i < 4; i++) acc[mt][nt][i] = 0.f;

    issue(0, 0);  CP_COMMIT();
    issue(1, 16); CP_COMMIT();
    issue(2, 32); CP_COMMIT();

    for (int it = 0; it < 16; it++) {
        CP_WAIT2();
        __syncthreads();
        const int st = it & 3;
        const float* Asl = As + st * A_STAGE;
        const float* Bsl = Bs + st * A_STAGE;
#pragma unroll
        for (int ks = 0; ks < 2; ks++) {
            const int kb = ks * 8;
            uint32_t af[4][4], bf[4][2];
            if (PERM) {
#pragma unroll
                for (int mt = 0; mt < 4; mt++) {
                    const int r0 = warp_m * 64 + mt * 16 + g;
                    const uint2 t0 = *(const uint2*)(Asl + (r0    ) * T + kb + 2 * q);
                    const uint2 t1 = *(const uint2*)(Asl + (r0 + 8) * T + kb + 2 * q);
                    af[mt][0] = t0.x; af[mt][2] = t0.y;
                    af[mt][1] = t1.x; af[mt][3] = t1.y;
                }
#pragma unroll
                for (int nt = 0; nt < 4; nt++) {
                    const int c0 = warp_n * 32 + nt * 8 + g;
                    const uint2 tb = *(const uint2*)(Bsl + c0 * T + kb + 2 * q);
                    bf[nt][0] = tb.x; bf[nt][1] = tb.y;
                }
            } else {
#pragma unroll
                for (int mt = 0; mt < 4; mt++) {
                    const int r0 = warp_m * 64 + mt * 16 + g;
                    af[mt][0] = __float_as_uint(Asl[(r0    ) * T + kb + q]);
                    af[mt][1] = __float_as_uint(Asl[(r0 + 8) * T + kb + q]);
                    af[mt][2] = __float_as_uint(Asl[(r0    ) * T + kb + q + 4]);
                    af[mt][3] = __float_as_uint(Asl[(r0 + 8) * T + kb + q + 4]);
                }
#pragma unroll
                for (int nt = 0; nt < 4; nt++) {
                    const int c0 = warp_n * 32 + nt * 8 + g;
                    bf[nt][0] = __float_as_uint(Bsl[c0 * T + kb + q]);
                    bf[nt][1] = __float_as_uint(Bsl[c0 * T + kb + q + 4]);
                }
            }
#pragma unroll
            for (int mt = 0; mt < 4; mt++)
#pragma unroll
                for (int nt = 0; nt < 4; nt++)
                    mma_tf32(acc[mt][nt], af[mt], bf[nt]);
        }
        // refill buffer consumed LAST iteration — ordered by this iteration's
        // top-of-loop __syncthreads, so no second barrier needed.
        const int kn = (it + 3) * 16;
        if (kn < 256) issue((it + 3) & 3, kn);
        CP_COMMIT();
    }

#pragma unroll
    for (int mt = 0; mt < 4; mt++) {
#pragma unroll
        for (int rr = 0; rr < 2; rr++) {
            const int m = m0 + warp_m * 64 + mt * 16 + g + rr * 8;
            if (PERM) {
                const int part = n0 >> 8;
                const int chn  = n0 & 255;
                uint32_t* dst = (part == 0) ? g_q : (part == 1) ? g_k : g_v;
                const size_t base = (size_t)m * C_ + chn;
#pragma unroll
                for (int nt = 0; nt < 4; nt++) {
                    const int cl = warp_n * 32 + nt * 8 + 2 * q;
                    uint2 v;
                    v.x = pack_hl(acc[mt][nt][rr * 2 + 0] + bias[n0 + cl]);
                    v.y = pack_hl(acc[mt][nt][rr * 2 + 1] + bias[n0 + cl + 1]);
                    *(uint2*)(dst + base + cl) = v;
                }
            } else {
                const size_t base = (size_t)token_of(m) * C_ + n0;
#pragma unroll
                for (int nt = 0; nt < 4; nt++) {
                    const int cl = warp_n * 32 + nt * 8 + 2 * q;
                    float2 v;
                    v.x = acc[mt][nt][rr * 2 + 0] + bias[n0 + cl];
                    v.y = acc[mt][nt][rr * 2 + 1] + bias[n0 + cl + 1];
                    *(float2*)(out + base + cl) = v;
                }
            }
        }
    }
}

// ---------------------------------------------------------------------------
// Attention (R15 exact: R11 body, launch_bounds(128,6)).
// ---------------------------------------------------------------------------
#define ATTN_U32 6912
#define ATTN_SMEM_B (ATTN_U32 * 4)

__global__ __launch_bounds__(128, 6) void attn_mma() {
    const int bwh = blockIdx.x;
    const int bw  = bwh >> 3;
    const int h   = bwh & 7;

    extern __shared__ uint32_t su[];
    uint32_t* Vb0  = su;
    uint32_t* Vb1  = su + 1184;
    float*    S    = (float*)(su + 2368);
    float*    sinv = (float*)(su + 2368 + 4480);

    const int tid  = threadIdx.x;
    const int lane = tid & 31;
    const int w    = tid >> 5;
    const int q    = lane & 3;
    const int g    = lane >> 2;
    const size_t ebase = (size_t)bw * WS2_ * C_ + h * HD_;

    for (int idx = tid; idx < WS2_ * 32; idx += 128) {
        const int i = idx >> 5, c = idx & 31;
        const uint32_t e = g_v[ebase + (size_t)i * C_ + c];
        ((unsigned short*)Vb0)[c * 74 + i] = (unsigned short)(e >> 16);
        ((unsigned short*)Vb1)[c * 74 + i] = (unsigned short)(e & 0xffffu);
    }
    for (int idx = tid; idx < 32 * 15; idx += 128) {
        const int d = idx / 15, j = 49 + idx % 15;
        ((unsigned short*)Vb0)[d * 74 + j] = 0;
        ((unsigned short*)Vb1)[d * 74 + j] = 0;
    }
    for (int idx = tid; idx < 256; idx += 128) {
        const int row = idx >> 2, cc = 56 + (idx & 3) * 2;
        *(float2*)&S[row * 70 + cc] = make_float2(0.f, 0.f);
    }

    const int r   = w * 16 + g;
    const int rc  = (r < 48) ? r : 48;
    const int rc8 = (r + 8 < 48) ? r + 8 : 48;
    const uint32_t* qrow  = g_q + ebase + (size_t)rc  * C_;
    const uint32_t* qrow8 = g_q + ebase + (size_t)rc8 * C_;

    float acc[7][4];
#pragma unroll
    for (int nt = 0; nt < 7; nt++)
#pragma unroll
        for (int i = 0; i < 4; i++) acc[nt][i] = 0.f;

#pragma unroll
    for (int ks = 0; ks < 2; ks++) {
        const int k0 = ks * 16 + 2 * q;
        const uint2 e00 = *(const uint2*)(qrow  + k0);
        const uint2 e10 = *(const uint2*)(qrow8 + k0);
        const uint2 e01 = *(const uint2*)(qrow  + k0 + 8);
        const uint2 e11 = *(const uint2*)(qrow8 + k0 + 8);
        uint32_t ah[4], al[4];
        ah[0] = HIPAIR(e00.x, e00.y);  al[0] = LOPAIR(e00.x, e00.y);
        ah[1] = HIPAIR(e10.x, e10.y);  al[1] = LOPAIR(e10.x, e10.y);
        ah[2] = HIPAIR(e01.x, e01.y);  al[2] = LOPAIR(e01.x, e01.y);
        ah[3] = HIPAIR(e11.x, e11.y);  al[3] = LOPAIR(e11.x, e11.y);
#pragma unroll
        for (int nt = 0; nt < 7; nt++) {
            const int n  = nt * 8 + g;
            const int nc = (n < 48) ? n : 48;
            const uint32_t* krow = g_k + ebase + (size_t)nc * C_;
            const uint2 f0 = *(const uint2*)(krow + k0);
            const uint2 f1 = *(const uint2*)(krow + k0 + 8);
            uint32_t bh[2], bl[2];
            bh[0] = HIPAIR(f0.x, f0.y);  bl[0] = LOPAIR(f0.x, f0.y);
            bh[1] = HIPAIR(f1.x, f1.y);  bl[1] = LOPAIR(f1.x, f1.y);
            mma_bf16(acc[nt], ah, bh);
            mma_bf16(acc[nt], ah, bl);
            mma_bf16(acc[nt], al, bh);
        }
    }

    const float scale = 0.17677669529663687f;
#pragma unroll
    for (int nt = 0; nt < 7; nt++) {
        *(float2*)&S[r * 70 + nt * 8 + 2 * q] =
            make_float2(acc[nt][0] * scale, acc[nt][1] * scale);
        *(float2*)&S[(r + 8) * 70 + nt * 8 + 2 * q] =
            make_float2(acc[nt][2] * scale, acc[nt][3] * scale);
    }
    __syncthreads();

    {
        const int row  = tid >> 1;
        const int part = tid & 1;
        const bool act = row < WS2_;
        float* rp = S + row * 70;
        const int j0 = part * 25;
        const int j1 = part ? WS2_ : 25;
        float sum = 0.f;
        if (act)
            for (int j = j0; j < j1; j++) {
                const float e = __expf(rp[j]);
                rp[j] = e;
                sum += e;
            }
        sum += __shfl_xor_sync(0xFFFFFFFF, sum, 1);
        if (act && part == 0) sinv[row] = __frcp_rn(sum);
    }
    __syncthreads();

    float o[4][4];
#pragma unroll
    for (int nt = 0; nt < 4; nt++)
#pragma unroll
        for (int i = 0; i < 4; i++) o[nt][i] = 0.f;

#pragma unroll
    for (int ks = 0; ks < 4; ks++) {
        const int kb = ks * 16;
        const float2 s00 = *(const float2*)&S[r * 70 + kb + 2 * q];
        const float2 s10 = *(const float2*)&S[(r + 8) * 70 + kb + 2 * q];
        const float2 s01 = *(const float2*)&S[r * 70 + kb + 8 + 2 * q];
        const float2 s11 = *(const float2*)&S[(r + 8) * 70 + kb + 8 + 2 * q];
        const float h00x = bf2f(s00.x), h00y = bf2f(s00.y);
        const float h10x = bf2f(s10.x), h10y = bf2f(s10.y);
        const float h01x = bf2f(s01.x), h01y = bf2f(s01.y);
        const float h11x = bf2f(s11.x), h11y = bf2f(s11.y);
        uint32_t ph[4] = { pkbf(h00x, h00y), pkbf(h10x, h10y),
                           pkbf(h01x, h01y), pkbf(h11x, h11y) };
        uint32_t pl[4] = { pkbf(s00.x - h00x, s00.y - h00y),
                           pkbf(s10.x - h10x, s10.y - h10y),
                           pkbf(s01.x - h01x, s01.y - h01y),
                           pkbf(s11.x - h11x, s11.y - h11y) };
        const int ub = ks * 8;
#pragma unroll
        for (int nt = 0; nt < 4; nt++) {
            const int cr = (nt * 8 + g) * 37 + ub;
            uint32_t vb0[2] = { Vb0[cr + q], Vb0[cr + 4 + q] };
            uint32_t vb1[2] = { Vb1[cr + q], Vb1[cr + 4 + q] };
            mma_bf16(o[nt], ph, vb0);
            mma_bf16(o[nt], ph, vb1);
            mma_bf16(o[nt], pl, vb0);
        }
    }

    if (r < WS2_) {
        const float iv = sinv[r];
#pragma unroll
        for (int nt = 0; nt < 4; nt++) {
            const int col = h * HD_ + nt * 8 + 2 * q;
            float2 v = make_float2(rtf(o[nt][0] * iv), rtf(o[nt][1] * iv));
            *(float2*)(g_o + (size_t)(bw * WS2_ + r) * C_ + col) = v;
        }
    }
    if (r + 8 < WS2_) {
        const float iv = sinv[r + 8];
#pragma unroll
        for (int nt = 0; nt < 4; nt++) {
            const int col = h * HD_ + nt * 8 + 2 * q;
            float2 v = make_float2(rtf(o[nt][2] * iv), rtf(o[nt][3] * iv));
            *(float2*)(g_o + (size_t)(bw * WS2_ + r + 8) * C_ + col) = v;
        }
    }
}

// ---------------------------------------------------------------------------
extern "C" void kernel_launch(void* const* d_in, const int* in_sizes, int n_in,
                              void* d_out, int out_size) {
    const float* x      = (const float*)d_in[0];
    const float* qkv_w  = (const float*)d_in[1];
    const float* qkv_b  = (const float*)d_in[2];
    const float* proj_w = (const float*)d_in[3];
    const float* proj_b = (const float*)d_in[4];
    float* out = (float*)d_out;

    constexpr int SM1 = 4 * 2 * 128 * 24 * 4;   // 98304 B (qkv, 4 stages)
    constexpr int SM0 = 4 * 2 * 128 * 20 * 4;   // 81920 B (proj, 4 stages)
    cudaFuncSetAttribute(mma_gemm<1>, cudaFuncAttributeMaxDynamicSharedMemorySize, SM1);
    cudaFuncSetAttribute(mma_gemm<0>, cudaFuncAttributeMaxDynamicSharedMemorySize, SM0);
    cudaFuncSetAttribute(attn_mma,    cudaFuncAttributeMaxDynamicSharedMemorySize, ATTN_SMEM_B);

    prep_all<<<PREP_TOTAL / 256, 256>>>(x, qkv_w, proj_w);

    mma_gemm<1><<<dim3(768 / 128, M_ / 128), 256, SM1>>>(qkv_b, nullptr);
    attn_mma<<<BW_ * NH_, 128, ATTN_SMEM_B>>>();
    mma_gemm<0><<<dim3(256 / 128, M_ / 128), 256, SM0>>>(proj_b, out);
}

// round 17
// speedup vs baseline: 1.0416x; 1.0416x over previous
#include <cuda_runtime.h>
#include <cuda_bf16.h>
#include <cstdint>

// ---------------------------------------------------------------------------
// LocallyGroupedAttn. R17 = R15 (598.1us best) + proj GEMM 3-stage BK=32
// single-sync ring (removes 1 of 2 barriers/iter). qkv/attn/prep unchanged.
// ---------------------------------------------------------------------------

#define B_    8
#define H_    112
#define W_    112
#define C_    256
#define WS_   7
#define NH_   8
#define HD_   32
#define WS2_  49
#define BW_   (B_ * 16 * 16)     // 2048
#define M_    (BW_ * WS2_)       // 100352

__device__ uint32_t g_q[M_ * C_];     // packed bf16 hi|lo per element
__device__ uint32_t g_k[M_ * C_];
__device__ uint32_t g_v[M_ * C_];
__device__ float    g_o[M_ * C_];     // rounded+gathered x, then attn output
__device__ float    g_wq[768 * C_];   // rounded + k-permuted qkv weight
__device__ float    g_wp[C_ * C_];    // rounded proj weight

__device__ __forceinline__ int token_of(int m) {
    int bw  = m / WS2_;
    int t   = m - bw * WS2_;
    int b   = bw >> 8;
    int win = bw & 255;
    int ty  = t / WS_;
    int tx  = t - ty * WS_;
    int y   = (win >> 4) * WS_ + ty;
    int x   = (win & 15) * WS_ + tx;
    return (b * H_ + y) * W_ + x;
}

__device__ __forceinline__ float rtf(float f) {
    uint32_t u;
    asm("cvt.rna.tf32.f32 %0, %1;" : "=r"(u) : "f"(f));
    return __uint_as_float(u);
}

__device__ __forceinline__ uint32_t smem_u32(const void* p) {
    uint32_t a;
    asm("{ .reg .u64 t; cvta.to.shared.u64 t, %1; cvt.u32.u64 %0, t; }" : "=r"(a) : "l"(p));
    return a;
}

__device__ __forceinline__ void cp16(void* dst, const void* src) {
    asm volatile("cp.async.cg.shared.global [%0], [%1], 16;"
                 :: "r"(smem_u32(dst)), "l"(src));
}
#define CP_COMMIT() asm volatile("cp.async.commit_group;" ::: "memory")
#define CP_WAIT1()  asm volatile("cp.async.wait_group 1;" ::: "memory")

__device__ __forceinline__ void mma_tf32(float c[4], const uint32_t a[4], const uint32_t b[2]) {
    asm volatile(
        "mma.sync.aligned.m16n8k8.row.col.f32.tf32.tf32.f32 "
        "{%0,%1,%2,%3}, {%4,%5,%6,%7}, {%8,%9}, {%0,%1,%2,%3};"
        : "+f"(c[0]), "+f"(c[1]), "+f"(c[2]), "+f"(c[3])
        : "r"(a[0]), "r"(a[1]), "r"(a[2]), "r"(a[3]), "r"(b[0]), "r"(b[1]));
}

__device__ __forceinline__ void mma_bf16(float c[4], const uint32_t a[4], const uint32_t b[2]) {
    asm volatile(
        "mma.sync.aligned.m16n8k16.row.col.f32.bf16.bf16.f32 "
        "{%0,%1,%2,%3}, {%4,%5,%6,%7}, {%8,%9}, {%0,%1,%2,%3};"
        : "+f"(c[0]), "+f"(c[1]), "+f"(c[2]), "+f"(c[3])
        : "r"(a[0]), "r"(a[1]), "r"(a[2]), "r"(a[3]), "r"(b[0]), "r"(b[1]));
}

__device__ __forceinline__ uint32_t pkbf(float lo, float hi) {
    __nv_bfloat162 t = __floats2bfloat162_rn(lo, hi);
    return *(uint32_t*)&t;
}
__device__ __forceinline__ float bf2f(float x) {
    return __bfloat162float(__float2bfloat16_rn(x));
}
__device__ __forceinline__ uint32_t pack_hl(float f) {
    __nv_bfloat16 h = __float2bfloat16_rn(f);
    float hf = __bfloat162float(h);
    __nv_bfloat16 l = __float2bfloat16_rn(f - hf);
    return ((uint32_t)__bfloat16_as_ushort(h) << 16) | (uint32_t)__bfloat16_as_ushort(l);
}
#define HIPAIR(w0, w1) __byte_perm((w0), (w1), 0x7632)
#define LOPAIR(w0, w1) __byte_perm((w0), (w1), 0x5410)

// ---------------------------------------------------------------------------
// Fused prepass (R13/R15)
// ---------------------------------------------------------------------------
#define PREP_X_CNT (M_ * 32)
#define PREP_WQ_CNT (768 * 32)
#define PREP_WP_CNT 16384
#define PREP_TOTAL (PREP_X_CNT + PREP_WQ_CNT + PREP_WP_CNT)

__global__ __launch_bounds__(256) void prep_all(const float* __restrict__ x,
                                                const float* __restrict__ qkv_w,
                                                const float* __restrict__ proj_w) {
    const int idx = blockIdx.x * 256 + threadIdx.x;
    if (idx < PREP_X_CNT) {
        const int m   = idx >> 5;
        const int grp = idx & 31;
        const float* src = x + (size_t)token_of(m) * C_ + grp * 8;
        const float4 a = *(const float4*)src;
        const float4 b = *(const float4*)(src + 4);
        float4 o0 = make_float4(rtf(a.x), rtf(b.x), rtf(a.y), rtf(b.y));
        float4 o1 = make_float4(rtf(a.z), rtf(b.z), rtf(a.w), rtf(b.w));
        float* dst = g_o + (size_t)m * C_ + grp * 8;
        *(float4*)dst       = o0;
        *(float4*)(dst + 4) = o1;
    } else if (idx < PREP_X_CNT + PREP_WQ_CNT) {
        const int j = idx - PREP_X_CNT;
        const int n = j >> 5, grp = j & 31;
        const float* src = qkv_w + (size_t)n * C_ + grp * 8;
        const float4 a = *(const float4*)src;
        const float4 b = *(const float4*)(src + 4);
        float4 o0 = make_float4(rtf(a.x), rtf(b.x), rtf(a.y), rtf(b.y));
        float4 o1 = make_float4(rtf(a.z), rtf(b.z), rtf(a.w), rtf(b.w));
        float* dst = g_wq + (size_t)n * C_ + grp * 8;
        *(float4*)dst       = o0;
        *(float4*)(dst + 4) = o1;
    } else {
        const int j = idx - PREP_X_CNT - PREP_WQ_CNT;
        const float4 v = ((const float4*)proj_w)[j];
        ((float4*)g_wp)[j] = make_float4(rtf(v.x), rtf(v.y), rtf(v.z), rtf(v.w));
    }
}

// ---------------------------------------------------------------------------
// qkv GEMM (R15 exact): 128x128, BK=32, 2-stage, 2 syncs/iter, 2 CTAs/SM.
// ---------------------------------------------------------------------------
__global__ __launch_bounds__(256, 2) void qkv_gemm(const float* __restrict__ bias) {
    constexpr int T       = 40;
    constexpr int STAGE_F = 128 * T;
    extern __shared__ char dsm[];
    float* As = (float*)dsm;
    float* Bs = As + 2 * STAGE_F;

    const int tid    = threadIdx.x;
    const int lane   = tid & 31;
    const int wid    = tid >> 5;
    const int warp_m = wid & 1;
    const int warp_n = wid >> 1;
    const int q      = lane & 3;
    const int g      = lane >> 2;
    const int n0     = blockIdx.x * 128;
    const int m0     = blockIdx.y * 128;

    auto issue = [&](int st, int k0) {
        float* Ad = As + st * STAGE_F;
        float* Bd = Bs + st * STAGE_F;
#pragma unroll
        for (int l = 0; l < 4; l++) {
            const int id  = tid + l * 256;
            const int row = id >> 3;
            const int c   = id & 7;
            cp16(Ad + row * T + c * 4, g_o  + (size_t)(m0 + row) * C_ + k0 + c * 4);
            cp16(Bd + row * T + c * 4, g_wq + (size_t)(n0 + row) * C_ + k0 + c * 4);
        }
    };

    float acc[4][4][4];
#pragma unroll
    for (int mt = 0; mt < 4; mt++)
#pragma unroll
        for (int nt = 0; nt < 4; nt++)
#pragma unroll
            for (int i = 0; i < 4; i++) acc[mt][nt][i] = 0.f;

    issue(0, 0);  CP_COMMIT();
    issue(1, 32); CP_COMMIT();

    for (int it = 0; it < 8; it++) {
        CP_WAIT1();
        __syncthreads();
        const float* Asl = As + (it & 1) * STAGE_F;
        const float* Bsl = Bs + (it & 1) * STAGE_F;
#pragma unroll
        for (int ks = 0; ks < 4; ks++) {
            const int kb = ks * 8;
            uint32_t af[4][4], bf[4][2];
#pragma unroll
            for (int mt = 0; mt < 4; mt++) {
                const int r0 = warp_m * 64 + mt * 16 + g;
                const uint2 t0 = *(const uint2*)(Asl + (r0    ) * T + kb + 2 * q);
                const uint2 t1 = *(const uint2*)(Asl + (r0 + 8) * T + kb + 2 * q);
                af[mt][0] = t0.x; af[mt][2] = t0.y;
                af[mt][1] = t1.x; af[mt][3] = t1.y;
            }
#pragma unroll
            for (int nt = 0; nt < 4; nt++) {
                const int c0 = warp_n * 32 + nt * 8 + g;
                const uint2 tb = *(const uint2*)(Bsl + c0 * T + kb + 2 * q);
                bf[nt][0] = tb.x; bf[nt][1] = tb.y;
            }
#pragma unroll
            for (int mt = 0; mt < 4; mt++)
#pragma unroll
                for (int nt = 0; nt < 4; nt++)
                    mma_tf32(acc[mt][nt], af[mt], bf[nt]);
        }
        __syncthreads();
        const int kn = (it + 2) * 32;
        if (kn < 256) issue(it & 1, kn);
        CP_COMMIT();
    }

#pragma unroll
    for (int mt = 0; mt < 4; mt++) {
#pragma unroll
        for (int rr = 0; rr < 2; rr++) {
            const int m = m0 + warp_m * 64 + mt * 16 + g + rr * 8;
            const int part = n0 >> 8;
            const int chn  = n0 & 255;
            uint32_t* dst = (part == 0) ? g_q : (part == 1) ? g_k : g_v;
            const size_t base = (size_t)m * C_ + chn;
#pragma unroll
            for (int nt = 0; nt < 4; nt++) {
                const int cl = warp_n * 32 + nt * 8 + 2 * q;
                uint2 v;
                v.x = pack_hl(acc[mt][nt][rr * 2 + 0] + bias[n0 + cl]);
                v.y = pack_hl(acc[mt][nt][rr * 2 + 1] + bias[n0 + cl + 1]);
                *(uint2*)(dst + base + cl) = v;
            }
        }
    }
}

// ---------------------------------------------------------------------------
// proj GEMM (R17): 128x128, BK=32, 3-stage ring, ONE sync/iter, 2 CTAs/SM.
// Refill target (it+2)%3 was consumed in iteration it-1 -> ordered by the
// top-of-loop barrier of iteration it.
// ---------------------------------------------------------------------------
__global__ __launch_bounds__(256, 2) void proj_gemm(const float* __restrict__ bias,
                                                    float* __restrict__ out) {
    constexpr int T       = 36;
    constexpr int STAGE_F = 128 * T;
    extern __shared__ char dsm[];
    float* As = (float*)dsm;                  // [3][128][36]
    float* Bs = As + 3 * STAGE_F;             // [3][128][36]

    const int tid    = threadIdx.x;
    const int lane   = tid & 31;
    const int wid    = tid >> 5;
    const int warp_m = wid & 1;
    const int warp_n = wid >> 1;
    const int q      = lane & 3;
    const int g      = lane >> 2;
    const int n0     = blockIdx.x * 128;
    const int m0     = blockIdx.y * 128;

    auto issue = [&](int st, int k0) {
        float* Ad = As + st * STAGE_F;
        float* Bd = Bs + st * STAGE_F;
#pragma unroll
        for (int l = 0; l < 4; l++) {
            const int id  = tid + l * 256;
            const int row = id >> 3;
            const int c   = id & 7;
            cp16(Ad + row * T + c * 4, g_o  + (size_t)(m0 + row) * C_ + k0 + c * 4);
            cp16(Bd + row * T + c * 4, g_wp + (size_t)(n0 + row) * C_ + k0 + c * 4);
        }
    };

    float acc[4][4][4];
#pragma unroll
    for (int mt = 0; mt < 4; mt++)
#pragma unroll
        for (int nt = 0; nt < 4; nt++)
#pragma unroll
            for (int i = 0; i < 4; i++) acc[mt][nt][i] = 0.f;

    issue(0, 0);  CP_COMMIT();
    issue(1, 32); CP_COMMIT();

    int st = 0;
    for (int it = 0; it < 8; it++) {
        CP_WAIT1();
        __syncthreads();
        const float* Asl = As + st * STAGE_F;
        const float* Bsl = Bs + st * STAGE_F;
#pragma unroll
        for (int ks = 0; ks < 4; ks++) {
            const int kb = ks * 8;
            uint32_t af[4][4], bf[4][2];
#pragma unroll
            for (int mt = 0; mt < 4; mt++) {
                const int r0 = warp_m * 64 + mt * 16 + g;
                af[mt][0] = __float_as_uint(Asl[(r0    ) * T + kb + q]);
                af[mt][1] = __float_as_uint(Asl[(r0 + 8) * T + kb + q]);
                af[mt][2] = __float_as_uint(Asl[(r0    ) * T + kb + q + 4]);
                af[mt][3] = __float_as_uint(Asl[(r0 + 8) * T + kb + q + 4]);
            }
#pragma unroll
            for (int nt = 0; nt < 4; nt++) {
                const int c0 = warp_n * 32 + nt * 8 + g;
                bf[nt][0] = __float_as_uint(Bsl[c0 * T + kb + q]);
                bf[nt][1] = __float_as_uint(Bsl[c0 * T + kb + q + 4]);
            }
#pragma unroll
            for (int mt = 0; mt < 4; mt++)
#pragma unroll
                for (int nt = 0; nt < 4; nt++)
                    mma_tf32(acc[mt][nt], af[mt], bf[nt]);
        }
        // single-sync refill: buffer (st+2)%3 was consumed last iteration
        const int kn = (it + 2) * 32;
        if (kn < 256) issue((st + 2) % 3, kn);
        CP_COMMIT();
        st = (st + 1) % 3;
    }

#pragma unroll
    for (int mt = 0; mt < 4; mt++) {
#pragma unroll
        for (int rr = 0; rr < 2; rr++) {
            const int m = m0 + warp_m * 64 + mt * 16 + g + rr * 8;
            const size_t base = (size_t)token_of(m) * C_ + n0;
#pragma unroll
            for (int nt = 0; nt < 4; nt++) {
                const int cl = warp_n * 32 + nt * 8 + 2 * q;
                float2 v;
                v.x = acc[mt][nt][rr * 2 + 0] + bias[n0 + cl];
                v.y = acc[mt][nt][rr * 2 + 1] + bias[n0 + cl + 1];
                *(float2*)(out + base + cl) = v;
            }
        }
    }
}

// ---------------------------------------------------------------------------
// Attention (R15 exact: R11 body, launch_bounds(128,6)).
// ---------------------------------------------------------------------------
#define ATTN_U32 6912
#define ATTN_SMEM_B (ATTN_U32 * 4)

__global__ __launch_bounds__(128, 6) void attn_mma() {
    const int bwh = blockIdx.x;
    const int bw  = bwh >> 3;
    const int h   = bwh & 7;

    extern __shared__ uint32_t su[];
    uint32_t* Vb0  = su;
    uint32_t* Vb1  = su + 1184;
    float*    S    = (float*)(su + 2368);
    float*    sinv = (float*)(su + 2368 + 4480);

    const int tid  = threadIdx.x;
    const int lane = tid & 31;
    const int w    = tid >> 5;
    const int q    = lane & 3;
    const int g    = lane >> 2;
    const size_t ebase = (size_t)bw * WS2_ * C_ + h * HD_;

    for (int idx = tid; idx < WS2_ * 32; idx += 128) {
        const int i = idx >> 5, c = idx & 31;
        const uint32_t e = g_v[ebase + (size_t)i * C_ + c];
        ((unsigned short*)Vb0)[c * 74 + i] = (unsigned short)(e >> 16);
        ((unsigned short*)Vb1)[c * 74 + i] = (unsigned short)(e & 0xffffu);
    }
    for (int idx = tid; idx < 32 * 15; idx += 128) {
        const int d = idx / 15, j = 49 + idx % 15;
        ((unsigned short*)Vb0)[d * 74 + j] = 0;
        ((unsigned short*)Vb1)[d * 74 + j] = 0;
    }
    for (int idx = tid; idx < 256; idx += 128) {
        const int row = idx >> 2, cc = 56 + (idx & 3) * 2;
        *(float2*)&S[row * 70 + cc] = make_float2(0.f, 0.f);
    }

    const int r   = w * 16 + g;
    const int rc  = (r < 48) ? r : 48;
    const int rc8 = (r + 8 < 48) ? r + 8 : 48;
    const uint32_t* qrow  = g_q + ebase + (size_t)rc  * C_;
    const uint32_t* qrow8 = g_q + ebase + (size_t)rc8 * C_;

    float acc[7][4];
#pragma unroll
    for (int nt = 0; nt < 7; nt++)
#pragma unroll
        for (int i = 0; i < 4; i++) acc[nt][i] = 0.f;

#pragma unroll
    for (int ks = 0; ks < 2; ks++) {
        const int k0 = ks * 16 + 2 * q;
        const uint2 e00 = *(const uint2*)(qrow  + k0);
        const uint2 e10 = *(const uint2*)(qrow8 + k0);
        const uint2 e01 = *(const uint2*)(qrow  + k0 + 8);
        const uint2 e11 = *(const uint2*)(qrow8 + k0 + 8);
        uint32_t ah[4], al[4];
        ah[0] = HIPAIR(e00.x, e00.y);  al[0] = LOPAIR(e00.x, e00.y);
        ah[1] = HIPAIR(e10.x, e10.y);  al[1] = LOPAIR(e10.x, e10.y);
        ah[2] = HIPAIR(e01.x, e01.y);  al[2] = LOPAIR(e01.x, e01.y);
        ah[3] = HIPAIR(e11.x, e11.y);  al[3] = LOPAIR(e11.x, e11.y);
#pragma unroll
        for (int nt = 0; nt < 7; nt++) {
            const int n  = nt * 8 + g;
            const int nc = (n < 48) ? n : 48;
            const uint32_t* krow = g_k + ebase + (size_t)nc * C_;
            const uint2 f0 = *(const uint2*)(krow + k0);
            const uint2 f1 = *(const uint2*)(krow + k0 + 8);
            uint32_t bh[2], bl[2];
            bh[0] = HIPAIR(f0.x, f0.y);  bl[0] = LOPAIR(f0.x, f0.y);
            bh[1] = HIPAIR(f1.x, f1.y);  bl[1] = LOPAIR(f1.x, f1.y);
            mma_bf16(acc[nt], ah, bh);
            mma_bf16(acc[nt], ah, bl);
            mma_bf16(acc[nt], al, bh);
        }
    }

    const float scale = 0.17677669529663687f;
#pragma unroll
    for (int nt = 0; nt < 7; nt++) {
        *(float2*)&S[r * 70 + nt * 8 + 2 * q] =
            make_float2(acc[nt][0] * scale, acc[nt][1] * scale);
        *(float2*)&S[(r + 8) * 70 + nt * 8 + 2 * q] =
            make_float2(acc[nt][2] * scale, acc[nt][3] * scale);
    }
    __syncthreads();

    {
        const int row  = tid >> 1;
        const int part = tid & 1;
        const bool act = row < WS2_;
        float* rp = S + row * 70;
        const int j0 = part * 25;
        const int j1 = part ? WS2_ : 25;
        float sum = 0.f;
        if (act)
            for (int j = j0; j < j1; j++) {
                const float e = __expf(rp[j]);
                rp[j] = e;
                sum += e;
            }
        sum += __shfl_xor_sync(0xFFFFFFFF, sum, 1);
        if (act && part == 0) sinv[row] = __frcp_rn(sum);
    }
    __syncthreads();

    float o[4][4];
#pragma unroll
    for (int nt = 0; nt < 4; nt++)
#pragma unroll
        for (int i = 0; i < 4; i++) o[nt][i] = 0.f;

#pragma unroll
    for (int ks = 0; ks < 4; ks++) {
        const int kb = ks * 16;
        const float2 s00 = *(const float2*)&S[r * 70 + kb + 2 * q];
        const float2 s10 = *(const float2*)&S[(r + 8) * 70 + kb + 2 * q];
        const float2 s01 = *(const float2*)&S[r * 70 + kb + 8 + 2 * q];
        const float2 s11 = *(const float2*)&S[(r + 8) * 70 + kb + 8 + 2 * q];
        const float h00x = bf2f(s00.x), h00y = bf2f(s00.y);
        const float h10x = bf2f(s10.x), h10y = bf2f(s10.y);
        const float h01x = bf2f(s01.x), h01y = bf2f(s01.y);
        const float h11x = bf2f(s11.x), h11y = bf2f(s11.y);
        uint32_t ph[4] = { pkbf(h00x, h00y), pkbf(h10x, h10y),
                           pkbf(h01x, h01y), pkbf(h11x, h11y) };
        uint32_t pl[4] = { pkbf(s00.x - h00x, s00.y - h00y),
                           pkbf(s10.x - h10x, s10.y - h10y),
                           pkbf(s01.x - h01x, s01.y - h01y),
                           pkbf(s11.x - h11x, s11.y - h11y) };
        const int ub = ks * 8;
#pragma unroll
        for (int nt = 0; nt < 4; nt++) {
            const int cr = (nt * 8 + g) * 37 + ub;
            uint32_t vb0[2] = { Vb0[cr + q], Vb0[cr + 4 + q] };
            uint32_t vb1[2] = { Vb1[cr + q], Vb1[cr + 4 + q] };
            mma_bf16(o[nt], ph, vb0);
            mma_bf16(o[nt], ph, vb1);
            mma_bf16(o[nt], pl, vb0);
        }
    }

    if (r < WS2_) {
        const float iv = sinv[r];
#pragma unroll
        for (int nt = 0; nt < 4; nt++) {
            const int col = h * HD_ + nt * 8 + 2 * q;
            float2 v = make_float2(rtf(o[nt][0] * iv), rtf(o[nt][1] * iv));
            *(float2*)(g_o + (size_t)(bw * WS2_ + r) * C_ + col) = v;
        }
    }
    if (r + 8 < WS2_) {
        const float iv = sinv[r + 8];
#pragma unroll
        for (int nt = 0; nt < 4; nt++) {
            const int col = h * HD_ + nt * 8 + 2 * q;
            float2 v = make_float2(rtf(o[nt][2] * iv), rtf(o[nt][3] * iv));
            *(float2*)(g_o + (size_t)(bw * WS2_ + r + 8) * C_ + col) = v;
        }
    }
}

// ---------------------------------------------------------------------------
extern "C" void kernel_launch(void* const* d_in, const int* in_sizes, int n_in,
                              void* d_out, int out_size) {
    const float* x      = (const float*)d_in[0];
    const float* qkv_w  = (const float*)d_in[1];
    const float* qkv_b  = (const float*)d_in[2];
    const float* proj_w = (const float*)d_in[3];
    const float* proj_b = (const float*)d_in[4];
    float* out = (float*)d_out;

    constexpr int SM1 = 2 * 2 * 128 * 40 * 4;   // 81920 B (qkv, 2-stage)
    constexpr int SM0 = 3 * 2 * 128 * 36 * 4;   // 110592 B (proj, 3-stage)
    cudaFuncSetAttribute(qkv_gemm,  cudaFuncAttributeMaxDynamicSharedMemorySize, SM1);
    cudaFuncSetAttribute(proj_gemm, cudaFuncAttributeMaxDynamicSharedMemorySize, SM0);
    cudaFuncSetAttribute(attn_mma,  cudaFuncAttributeMaxDynamicSharedMemorySize, ATTN_SMEM_B);

    prep_all<<<PREP_TOTAL / 256, 256>>>(x, qkv_w, proj_w);

    qkv_gemm<<<dim3(768 / 128, M_ / 128), 256, SM1>>>(qkv_b);
    attn_mma<<<BW_ * NH_, 128, ATTN_SMEM_B>>>();
    proj_gemm<<<dim3(256 / 128, M_ / 128), 256, SM0>>>(proj_b, out);
}